// round 15
// baseline (speedup 1.0000x reference)
#include <cuda_runtime.h>
#include <math_constants.h>
#include <cstdint>
#include <cuda_bf16.h>

namespace {
constexpr int B  = 4;
constexpr int S  = 4096;
constexpr int DM = 512;
constexpr int DH = 64;
constexpr int M  = B * S;     // 16384 rows
constexpr int QT = 256;       // query rows per tile (8 warps x 32)
constexpr int KB = 64;        // keys per k-block
constexpr int NT = S / QT;    // 16 q-tiles per batch
constexpr int CH = 8;         // k-blocks per chunk (512 keys)
constexpr int MAXC = 8;
constexpr int CPB  = 72;      // chunks per batch

// attn smem element counts (validated R10-R12)
constexpr int Q4_SZ = 4 * 513;          // uint4 per Q matrix (hi or lo)
constexpr int KW_SZ = 32 * 72;          // uint words per K matrix (hi or lo)
constexpr int K4_SZ = KW_SZ / 4;        // 576 uint4
constexpr int VP_SZ = 2112;             // float2 (V b-frag packed)
constexpr int V4_SZ = VP_SZ / 2;        // 1056 uint4
constexpr int SM_BYTES = 2 * Q4_SZ * 16 + 2 * KW_SZ * 4 + VP_SZ * 8;  // 100992

// proj smem: X (128x64 chunk) in A-frag layout, W (64x64) in B-frag layout
constexpr int PX4 = 4 * 257;            // uint4 per X matrix (hi or lo)
constexpr int PWW = 32 * 72;            // words per W matrix (hi or lo)
constexpr int PSM_BYTES = 2 * PX4 * 16 + 2 * PWW * 4;   // 51328

constexpr int NQTILES = M / QT;         // 64
constexpr int NKBLK   = M / KB;         // 256
}

// Pre-formatted operand buffers (static device globals — no allocs):
//  Q bf16 hi/lo in A-frag layout, per 256-row tile
__device__ uint4 g_qh4[(size_t)NQTILES * Q4_SZ];
__device__ uint4 g_ql4[(size_t)NQTILES * Q4_SZ];
//  K bf16 hi/lo in permuted-col B-frag layout, per 64-key block
__device__ uint4 g_kh4[(size_t)NKBLK * K4_SZ];
__device__ uint4 g_kl4[(size_t)NKBLK * K4_SZ];
//  V tf32 in packed B-frag layout, per 64-key block
__device__ uint4 g_vp4[(size_t)NKBLK * V4_SZ];
// Split-KV partials
__device__ float g_pO[(size_t)B * NT * MAXC * QT * DH];
__device__ float g_pl[(size_t)B * NT * MAXC * QT];

__device__ __forceinline__ float tf32_rn(float x) {
    uint32_t u;
    asm("cvt.rna.tf32.f32 %0, %1;" : "=r"(u) : "f"(x));
    return __uint_as_float(u);
}
// pack two floats to bf16x2 word: first arg -> low 16 bits (lower k index)
__device__ __forceinline__ uint32_t pack_bf16(float lo, float hi) {
    uint32_t r;
    asm("{ .reg .b16 l, h; cvt.rn.bf16.f32 l, %1; cvt.rn.bf16.f32 h, %2;"
        " mov.b32 %0, {l, h}; }" : "=r"(r) : "f"(lo), "f"(hi));
    return r;
}

// D[16x8] += A[16x8] * B[8x8]  (tf32, k8)
__device__ __forceinline__ void mma_tf32(float* d, const uint32_t* a,
                                         const uint32_t* b) {
    asm volatile(
        "mma.sync.aligned.m16n8k8.row.col.f32.tf32.tf32.f32 "
        "{%0,%1,%2,%3}, {%4,%5,%6,%7}, {%8,%9}, {%0,%1,%2,%3};"
        : "+f"(d[0]), "+f"(d[1]), "+f"(d[2]), "+f"(d[3])
        : "r"(a[0]), "r"(a[1]), "r"(a[2]), "r"(a[3]),
          "r"(b[0]), "r"(b[1]));
}
// D[16x8] += A[16x16] * B[16x8]  (bf16, k16)
__device__ __forceinline__ void mma_bf16(float* d, const uint32_t* a,
                                         const uint32_t* b) {
    asm volatile(
        "mma.sync.aligned.m16n8k16.row.col.f32.bf16.bf16.f32 "
        "{%0,%1,%2,%3}, {%4,%5,%6,%7}, {%8,%9}, {%0,%1,%2,%3};"
        : "+f"(d[0]), "+f"(d[1]), "+f"(d[2]), "+f"(d[3])
        : "r"(a[0]), "r"(a[1]), "r"(a[2]), "r"(a[3]),
          "r"(b[0]), "r"(b[1]));
}

// ===========================================================================
// Tensor-core projection: out = X @ W^T + b.  M=16384, N=64, K=512.
//   bf16 m16n8k16 3-term split, fp32 accum, CTA 128 rows, 3 CTAs/SM.
//   Epilogue writes PRE-FORMATTED operands for attn:
//     Q -> bf16 hi/lo A-frag layout; K -> bf16 hi/lo permuted B-frag layout;
//     V -> tf32 packed B-frag layout.  (C-frag word == frag word.)
// ===========================================================================
__global__ __launch_bounds__(256, 3) void proj_tc_kernel(
    const float* __restrict__ q_in, const float* __restrict__ k_in,
    const float* __restrict__ v_in,
    const float* __restrict__ Wq, const float* __restrict__ bq,
    const float* __restrict__ Wk, const float* __restrict__ bk,
    const float* __restrict__ Wv, const float* __restrict__ bv)
{
    extern __shared__ char psm[];
    uint4*    Xh4 = reinterpret_cast<uint4*>(psm);
    uint4*    Xl4 = Xh4 + PX4;
    uint32_t* Whw = reinterpret_cast<uint32_t*>(Xl4 + PX4);
    uint32_t* Wlw = Whw + PWW;
    uint32_t* Xhw = reinterpret_cast<uint32_t*>(Xh4);
    uint32_t* Xlw = reinterpret_cast<uint32_t*>(Xl4);

    const int which = blockIdx.y;
    const float* X    = (which == 0) ? q_in : (which == 1) ? k_in : v_in;
    const float* W    = (which == 0) ? Wq   : (which == 1) ? Wk   : Wv;
    const float* bias = (which == 0) ? bq   : (which == 1) ? bk   : bv;

    const int m0   = blockIdx.x * 128;
    const int tid  = threadIdx.x;
    const int lane = tid & 31;
    const int w    = tid >> 5;
    const int rq   = lane >> 2;
    const int cq   = lane & 3;

    float od[8][4];
#pragma unroll
    for (int n = 0; n < 8; n++)
#pragma unroll
        for (int r = 0; r < 4; r++) od[n][r] = 0.f;

    for (int k0 = 0; k0 < DM; k0 += 64) {
        __syncthreads();   // previous chunk's MMA reads done

        // ---- X chunk (128 rows x 64 k) -> A-frag layout, hi/lo split ----
#pragma unroll
        for (int it = 0; it < 8; it++) {
            int idx = tid + it * 256;      // 0..2047
            int row = idx >> 4;            // 0..127
            int c4  = idx & 15;
            float4 v = *reinterpret_cast<const float4*>(
                &X[(size_t)(m0 + row) * DM + k0 + c4 * 4]);
            float hx = __bfloat162float(__float2bfloat16(v.x));
            float hy = __bfloat162float(__float2bfloat16(v.y));
            float hz = __bfloat162float(__float2bfloat16(v.z));
            float hw = __bfloat162float(__float2bfloat16(v.w));
            uint32_t h0 = pack_bf16(hx, hy);
            uint32_t h1 = pack_bf16(hz, hw);
            uint32_t l0 = pack_bf16(v.x - hx, v.y - hy);
            uint32_t l1 = pack_bf16(v.z - hz, v.w - hw);
            int g    = c4 >> 2;
            int rg   = row >> 4;           // 0..7
            int rqf  = row & 7;
            int rbit = (row >> 3) & 1;
            int d2a  = 2 * (c4 & 3);
            int d2b  = d2a + 1;
            int base = g * 257 + rg * 32 + rqf * 4;
            int ca = (d2a >= 4 ? 2 : 0) + rbit;
            int cb = (d2b >= 4 ? 2 : 0) + rbit;
            Xhw[(base + (d2a & 3)) * 4 + ca] = h0;
            Xhw[(base + (d2b & 3)) * 4 + cb] = h1;
            Xlw[(base + (d2a & 3)) * 4 + ca] = l0;
            Xlw[(base + (d2b & 3)) * 4 + cb] = l1;
        }
        // ---- W chunk (64 n x 64 k) -> B-frag layout (identity cols) ----
#pragma unroll
        for (int it = 0; it < 4; it++) {
            int idx = tid + it * 256;      // 0..1023
            int n  = idx >> 4;
            int c4 = idx & 15;
            float4 v = *reinterpret_cast<const float4*>(
                &W[(size_t)n * DM + k0 + c4 * 4]);
            float hx = __bfloat162float(__float2bfloat16(v.x));
            float hy = __bfloat162float(__float2bfloat16(v.y));
            float hz = __bfloat162float(__float2bfloat16(v.z));
            float hw = __bfloat162float(__float2bfloat16(v.w));
            uint32_t h0 = pack_bf16(hx, hy);
            uint32_t h1 = pack_bf16(hz, hw);
            uint32_t l0 = pack_bf16(v.x - hx, v.y - hy);
            uint32_t l1 = pack_bf16(v.z - hz, v.w - hw);
            int g   = c4 >> 2;
            int nb  = n >> 3;
            int wk  = n & 7;
            int d2a = 2 * (c4 & 3), d2b = d2a + 1;
            int base = (g * 8 + nb) * 72;
            Whw[base + d2a * 8 + wk] = h0;
            Whw[base + d2b * 8 + wk] = h1;
            Wlw[base + d2a * 8 + wk] = l0;
            Wlw[base + d2b * 8 + wk] = l1;
        }
        __syncthreads();

        // ---- MMA: od += Xh*Wh + Xh*Wl + Xl*Wh  (1 m-frag per warp) ----
#pragma unroll
        for (int g = 0; g < 4; g++) {
            uint4 xh, xl;
            {
                int a = g * 257 + w * 32 + rq * 4 + cq;
                xh = Xh4[a];
                xl = Xl4[a];
            }
            const uint32_t* ah = reinterpret_cast<const uint32_t*>(&xh);
            const uint32_t* al = reinterpret_cast<const uint32_t*>(&xl);
#pragma unroll
            for (int n = 0; n < 8; n++) {
                uint32_t bh[2], bl[2];
                int a0 = (g * 8 + n) * 72 + cq * 8 + rq;
                bh[0] = Whw[a0];
                bh[1] = Whw[a0 + 32];
                bl[0] = Wlw[a0];
                bl[1] = Wlw[a0 + 32];
                mma_bf16(od[n], ah, bh);
                mma_bf16(od[n], ah, bl);
                mma_bf16(od[n], al, bh);
            }
        }
    }

    // ---- epilogue: write pre-formatted operands ----
    if (which == 0) {
        // Q: bf16 hi/lo A-frag words, scaled by 0.125.
        const int tile = blockIdx.x >> 1;       // row/256
        const int half = blockIdx.x & 1;
        uint32_t* qh = reinterpret_cast<uint32_t*>(g_qh4 + (size_t)tile * Q4_SZ);
        uint32_t* ql = reinterpret_cast<uint32_t*>(g_ql4 + (size_t)tile * Q4_SZ);
#pragma unroll
        for (int n = 0; n < 8; n++) {
            float b0 = bias[n * 8 + 2 * cq];
            float b1 = bias[n * 8 + 2 * cq + 1];
            int a = (n >> 1) * 513 + (half * 8 + w) * 32 + rq * 4 + cq;
#pragma unroll
            for (int rb = 0; rb < 2; rb++) {
                float x = (od[n][2 * rb + 0] + b0) * 0.125f;
                float y = (od[n][2 * rb + 1] + b1) * 0.125f;
                float hx = __bfloat162float(__float2bfloat16(x));
                float hy = __bfloat162float(__float2bfloat16(y));
                int widx = 4 * a + 2 * (n & 1) + rb;
                qh[widx] = pack_bf16(hx, hy);
                ql[widx] = pack_bf16(x - hx, y - hy);
            }
        }
    } else if (which == 1) {
        // K: bf16 hi/lo permuted-col B-frag words.
        uint32_t* kh = reinterpret_cast<uint32_t*>(g_kh4);
        uint32_t* kl = reinterpret_cast<uint32_t*>(g_kl4);
#pragma unroll
        for (int n = 0; n < 8; n++) {
            float b0 = bias[n * 8 + 2 * cq];
            float b1 = bias[n * 8 + 2 * cq + 1];
            int d2 = 4 * (n & 1) + cq;
#pragma unroll
            for (int rb = 0; rb < 2; rb++) {
                float x = od[n][2 * rb + 0] + b0;
                float y = od[n][2 * rb + 1] + b1;
                float hx = __bfloat162float(__float2bfloat16(x));
                float hy = __bfloat162float(__float2bfloat16(y));
                int row = m0 + 16 * w + rq + 8 * rb;
                int blk = row >> 6;
                int j   = row & 63;
                int nK  = j >> 3;
                int wk  = j & 7;
                int cst = (wk < 4) ? 2 * wk : 2 * wk - 7;
                size_t idx = (size_t)blk * KW_SZ
                           + (((n >> 1) * 8 + nK) * 72 + d2 * 8 + cst);
                kh[idx] = pack_bf16(hx, hy);
                kl[idx] = pack_bf16(x - hx, y - hy);
            }
        }
    } else {
        // V: tf32 values in packed B-frag layout.
        float* vp = reinterpret_cast<float*>(g_vp4);
#pragma unroll
        for (int n = 0; n < 8; n++) {
            float b0 = bias[n * 8 + 2 * cq];
            float b1 = bias[n * 8 + 2 * cq + 1];
#pragma unroll
            for (int r = 0; r < 4; r++) {
                float v = od[n][r] + ((r & 1) ? b1 : b0);
                int row = m0 + 16 * w + rq + 8 * (r >> 1);
                int blk = row >> 6;
                int j   = row & 63;
                int grp = j >> 3;
                int wk  = j & 7;
                int d7  = 2 * cq + (r & 1);
                size_t idx = (size_t)blk * (VP_SZ * 2)
                           + ((grp * 264 + n * 33 + d7 * 4 + (wk & 3)) * 2
                              + (wk >> 2));
                vp[idx] = tf32_rn(v);
            }
        }
    }
}

// ===========================================================================
// Tensor-core causal flash attention (compute identical to R10-R12);
// loaders are now straight uint4 copies of pre-formatted operands.
// ===========================================================================
__global__ __launch_bounds__(256, 1) void attn_tc_kernel()
{
    extern __shared__ char smc[];
    uint4*    Qh4 = reinterpret_cast<uint4*>(smc);          // [Q4_SZ]
    uint4*    Ql4 = Qh4 + Q4_SZ;                            // [Q4_SZ]
    uint32_t* Khw = reinterpret_cast<uint32_t*>(Ql4 + Q4_SZ);   // [KW_SZ]
    uint32_t* Klw = Khw + KW_SZ;                            // [KW_SZ]
    float2*   Vp2 = reinterpret_cast<float2*>(Klw + KW_SZ); // [VP_SZ]
    uint4*    Kh4s = reinterpret_cast<uint4*>(Khw);
    uint4*    Kl4s = reinterpret_cast<uint4*>(Klw);
    uint4*    Vp4s = reinterpret_cast<uint4*>(Vp2);

    const int tid  = threadIdx.x;
    const int lane = tid & 31;
    const int w    = tid >> 5;    // 0..7
    const int rq   = lane >> 2;   // 0..7
    const int cq   = lane & 3;    // 0..3

    const int b   = blockIdx.y;
    const int cid = (CPB - 1) - blockIdx.x;   // big tiles first
    int u = 0;
    while ((u + 1) * (u + 2) <= cid) u++;     // group u: tiles {2u,2u+1}, u+1 chunks
    const int off = cid - u * (u + 1);
    const int t   = 2 * u + off / (u + 1);
    const int ci  = off % (u + 1);
    const int nkb = 4 * t + 4;
    const int kb0 = ci * CH;
    const int kb1 = min(kb0 + CH, nkb);

    // ---- Q tile: straight copy of pre-formatted A-frags ----
    {
        const int tile = b * NT + t;
        const uint4* gqh = g_qh4 + (size_t)tile * Q4_SZ;
        const uint4* gql = g_ql4 + (size_t)tile * Q4_SZ;
        for (int i = tid; i < Q4_SZ; i += 256) {
            Qh4[i] = gqh[i];
            Ql4[i] = gql[i];
        }
    }

    float od[2][8][4];
    float l_acc[2][2] = {{0.f, 0.f}, {0.f, 0.f}};
#pragma unroll
    for (int mf = 0; mf < 2; mf++)
#pragma unroll
        for (int n = 0; n < 8; n++)
#pragma unroll
            for (int r = 0; r < 4; r++) od[mf][n][r] = 0.f;

    const int rbase = t * QT + w * 32;   // global q-row base for this warp

    for (int kb = kb0; kb < kb1; kb++) {
        __syncthreads();   // prev iter done reading K/V (Q visible, kb=kb0)

        // ---- K/V: straight copies of pre-formatted B-frags ----
        const int blk = b * (S / KB) + kb;
        {
            const uint4* gkh = g_kh4 + (size_t)blk * K4_SZ;
            const uint4* gkl = g_kl4 + (size_t)blk * K4_SZ;
            for (int i = tid; i < K4_SZ; i += 256) {
                Kh4s[i] = gkh[i];
                Kl4s[i] = gkl[i];
            }
            const uint4* gvp = g_vp4 + (size_t)blk * V4_SZ;
            for (int i = tid; i < V4_SZ; i += 256)
                Vp4s[i] = gvp[i];
        }
        __syncthreads();

        const int jb = kb * KB;
        if (jb > rbase + 31) continue;   // fully masked for this warp: skip

        // ---- S = Q K^T  (bf16 k16, 3-term split) ----
        float sd[2][8][4];
#pragma unroll
        for (int mf = 0; mf < 2; mf++)
#pragma unroll
            for (int n = 0; n < 8; n++)
#pragma unroll
                for (int r = 0; r < 4; r++) sd[mf][n][r] = 0.f;

#pragma unroll
        for (int g = 0; g < 4; g++) {
            uint4 qh[2], ql[2];
#pragma unroll
            for (int mf = 0; mf < 2; mf++) {
                int a = g * 513 + (w * 2 + mf) * 32 + rq * 4 + cq;
                qh[mf] = Qh4[a];
                ql[mf] = Ql4[a];
            }
            uint32_t bh[8][2], bl[8][2];
#pragma unroll
            for (int n = 0; n < 8; n++) {
                int a0 = (g * 8 + n) * 72 + cq * 8 + rq;
                bh[n][0] = Khw[a0];
                bh[n][1] = Khw[a0 + 32];
                bl[n][0] = Klw[a0];
                bl[n][1] = Klw[a0 + 32];
            }
#pragma unroll
            for (int mf = 0; mf < 2; mf++) {
                const uint32_t* ah = reinterpret_cast<const uint32_t*>(&qh[mf]);
                const uint32_t* al = reinterpret_cast<const uint32_t*>(&ql[mf]);
#pragma unroll
                for (int n = 0; n < 8; n++) {
                    mma_bf16(sd[mf][n], ah, bh[n]);
                    mma_bf16(sd[mf][n], ah, bl[n]);
                    mma_bf16(sd[mf][n], al, bh[n]);
                }
            }
        }

        // ---- softmax; build PV A-frags in-place (order {c0,c2,c1,c3}) ----
        const bool need_mask = (jb + KB - 1) > rbase;
        if (need_mask) {
#pragma unroll
            for (int mf = 0; mf < 2; mf++) {
                const int r0g = rbase + mf * 16 + rq;
                const int r1g = r0g + 8;
#pragma unroll
                for (int n = 0; n < 8; n++) {
                    int kA = jb + n * 8 + cq;
                    int kB = kA + 4;
                    float p0 = (kA <= r0g) ? tf32_rn(__expf(sd[mf][n][0])) : 0.f;
                    float p1 = (kB <= r0g) ? tf32_rn(__expf(sd[mf][n][1])) : 0.f;
                    float p2 = (kA <= r1g) ? tf32_rn(__expf(sd[mf][n][2])) : 0.f;
                    float p3 = (kB <= r1g) ? tf32_rn(__expf(sd[mf][n][3])) : 0.f;
                    l_acc[mf][0] += p0 + p1;
                    l_acc[mf][1] += p2 + p3;
                    sd[mf][n][0] = p0;
                    sd[mf][n][1] = p2;
                    sd[mf][n][2] = p1;
                    sd[mf][n][3] = p3;
                }
            }
        } else {
#pragma unroll
            for (int mf = 0; mf < 2; mf++) {
#pragma unroll
                for (int n = 0; n < 8; n++) {
                    float p0 = tf32_rn(__expf(sd[mf][n][0]));
                    float p1 = tf32_rn(__expf(sd[mf][n][1]));
                    float p2 = tf32_rn(__expf(sd[mf][n][2]));
                    float p3 = tf32_rn(__expf(sd[mf][n][3]));
                    l_acc[mf][0] += p0 + p1;
                    l_acc[mf][1] += p2 + p3;
                    sd[mf][n][0] = p0;
                    sd[mf][n][1] = p2;
                    sd[mf][n][2] = p1;
                    sd[mf][n][3] = p3;
                }
            }
        }

        // ---- O += P V  (tf32; A-frags straight from sd registers) ----
#pragma unroll
        for (int grp = 0; grp < 8; grp++) {
            float2 v2[8];
#pragma unroll
            for (int n2 = 0; n2 < 8; n2++)
                v2[n2] = Vp2[grp * 264 + n2 * 33 + rq * 4 + cq];
#pragma unroll
            for (int mf = 0; mf < 2; mf++) {
                const uint32_t* ap = reinterpret_cast<const uint32_t*>(sd[mf][grp]);
#pragma unroll
                for (int n2 = 0; n2 < 8; n2++)
                    mma_tf32(od[mf][n2], ap,
                             reinterpret_cast<const uint32_t*>(&v2[n2]));
            }
        }
    }

    // ---- epilogue: write unnormalized partial O and l ----
    const size_t pb = ((size_t)(b * NT + t)) * MAXC + ci;
#pragma unroll
    for (int mf = 0; mf < 2; mf++)
#pragma unroll
        for (int rb = 0; rb < 2; rb++) {
            int rloc = w * 32 + mf * 16 + rq + rb * 8;
            float* dst = &g_pO[(pb * QT + rloc) * DH];
#pragma unroll
            for (int n2 = 0; n2 < 8; n2++)
                *reinterpret_cast<float2*>(&dst[n2 * 8 + 2 * cq]) =
                    make_float2(od[mf][n2][rb * 2], od[mf][n2][rb * 2 + 1]);
            float v = l_acc[mf][rb];
            v += __shfl_xor_sync(0xffffffffu, v, 1);
            v += __shfl_xor_sync(0xffffffffu, v, 2);
            if (cq == 0) g_pl[pb * QT + rloc] = v;
        }
}

// ===========================================================================
// Combine: out = sum_c O_c / sum_c l_c
// ===========================================================================
__global__ __launch_bounds__(256) void combine_kernel(float* __restrict__ out)
{
    const int t   = blockIdx.x;
    const int b   = blockIdx.y;
    const int nch = t / 2 + 1;
    const int row = threadIdx.x;

    const size_t pb0 = ((size_t)(b * NT + t)) * MAXC;

    float L = 0.f;
    float acc[DH];
#pragma unroll
    for (int c = 0; c < DH; c++) acc[c] = 0.f;

    for (int c = 0; c < nch; c++) {
        L += g_pl[(pb0 + c) * QT + row];
        const float* po = &g_pO[((pb0 + c) * QT + row) * DH];
#pragma unroll
        for (int c4 = 0; c4 < 16; c4++) {
            float4 o = *reinterpret_cast<const float4*>(&po[c4 * 4]);
            acc[c4 * 4 + 0] += o.x;
            acc[c4 * 4 + 1] += o.y;
            acc[c4 * 4 + 2] += o.z;
            acc[c4 * 4 + 3] += o.w;
        }
    }

    const float inv = 1.f / L;
    float* ob = out + ((size_t)b * S + t * QT + row) * DH;
#pragma unroll
    for (int c4 = 0; c4 < 16; c4++) {
        float4 o;
        o.x = acc[c4 * 4 + 0] * inv;
        o.y = acc[c4 * 4 + 1] * inv;
        o.z = acc[c4 * 4 + 2] * inv;
        o.w = acc[c4 * 4 + 3] * inv;
        *reinterpret_cast<float4*>(&ob[c4 * 4]) = o;
    }
}

// ===========================================================================
extern "C" void kernel_launch(void* const* d_in, const int* in_sizes, int n_in,
                              void* d_out, int out_size) {
    const float* q_in = (const float*)d_in[0];
    const float* k_in = (const float*)d_in[1];
    const float* v_in = (const float*)d_in[2];
    const float* Wq   = (const float*)d_in[3];
    const float* bq   = (const float*)d_in[4];
    const float* Wk   = (const float*)d_in[5];
    const float* bk   = (const float*)d_in[6];
    const float* Wv   = (const float*)d_in[7];
    const float* bv   = (const float*)d_in[8];

    cudaFuncSetAttribute(attn_tc_kernel,
                         cudaFuncAttributeMaxDynamicSharedMemorySize, SM_BYTES);
    cudaFuncSetAttribute(proj_tc_kernel,
                         cudaFuncAttributeMaxDynamicSharedMemorySize, PSM_BYTES);

    dim3 pg(M / 128, 3);             // 128 x 3 = 384 CTAs, one wave @ 3/SM
    proj_tc_kernel<<<pg, 256, PSM_BYTES>>>(q_in, k_in, v_in,
                                           Wq, bq, Wk, bk, Wv, bv);

    dim3 ag(CPB, B);                 // 72 x 4 = 288 chunk CTAs, <=8 iters each
    attn_tc_kernel<<<ag, 256, SM_BYTES>>>();

    dim3 cg(NT, B);                  // 16 x 4 combine CTAs
    combine_kernel<<<cg, 256>>>((float*)d_out);
}